// round 1
// baseline (speedup 1.0000x reference)
#include <cuda_runtime.h>
#include <math.h>

#define T_DIM   64
#define B_DIM   512
#define D_DIM   768
#define H_DIM   12
#define HD_DIM  64
#define M_ROWS  (T_DIM * B_DIM)    /* 32768 */
#define QKV_N   (3 * D_DIM)        /* 2304  */

/* Scratch (device globals; no allocation allowed in kernel_launch) */
__device__ float g_qkv[M_ROWS * QKV_N];   /* ~302 MB */
__device__ float g_ctx[M_ROWS * D_DIM];   /* ~100 MB */
__device__ float g_out[M_ROWS * D_DIM];   /* ~100 MB */

/* ------------------------------------------------------------------ */
/* GEMM: C[M,N] = A[M,K] @ Bw[N,K]^T + bias[N].  A,Bw both K-major.   */
/* 64x64 tile, KT=16, 256 threads, 4x4 microtile, float4 everywhere.  */
/* ------------------------------------------------------------------ */
#define TILE 64
#define KT   16

__global__ __launch_bounds__(256) void gemm_bias_kernel(
    const float* __restrict__ A, const float* __restrict__ Bw,
    const float* __restrict__ bias, float* __restrict__ C,
    int M, int N, int K)
{
    __shared__ float As[KT][TILE + 4];  /* [k][m], +4 keeps float4 alignment */
    __shared__ float Bs[KT][TILE + 4];  /* [k][n] */

    const int tid = threadIdx.x;
    const int bm  = blockIdx.y * TILE;
    const int bn  = blockIdx.x * TILE;

    /* loader mapping: one float4 of A and of Bw per k-tile per thread */
    const int lr = tid >> 2;          /* 0..63 row in tile   */
    const int lk = (tid & 3) << 2;    /* 0,4,8,12 k offset   */
    const float* Ap = A  + (size_t)(bm + lr) * K + lk;
    const float* Bp = Bw + (size_t)(bn + lr) * K + lk;

    /* compute mapping */
    const int m0 = (tid >> 4) << 2;   /* 0..60 */
    const int n0 = (tid & 15) << 2;   /* 0..60 */

    float acc[4][4] = {};

    for (int k0 = 0; k0 < K; k0 += KT) {
        float4 av = *(const float4*)(Ap + k0);
        float4 bv = *(const float4*)(Bp + k0);
        As[lk + 0][lr] = av.x; As[lk + 1][lr] = av.y;
        As[lk + 2][lr] = av.z; As[lk + 3][lr] = av.w;
        Bs[lk + 0][lr] = bv.x; Bs[lk + 1][lr] = bv.y;
        Bs[lk + 2][lr] = bv.z; Bs[lk + 3][lr] = bv.w;
        __syncthreads();

#pragma unroll
        for (int kk = 0; kk < KT; kk++) {
            float4 a = *(const float4*)&As[kk][m0];
            float4 b = *(const float4*)&Bs[kk][n0];
            float am[4] = {a.x, a.y, a.z, a.w};
            float bb[4] = {b.x, b.y, b.z, b.w};
#pragma unroll
            for (int i = 0; i < 4; i++)
#pragma unroll
                for (int j = 0; j < 4; j++)
                    acc[i][j] += am[i] * bb[j];
        }
        __syncthreads();
    }

#pragma unroll
    for (int i = 0; i < 4; i++) {
#pragma unroll
        for (int j = 0; j < 4; j++) {
            C[(size_t)(bm + m0 + i) * N + (bn + n0 + j)] =
                acc[i][j] + bias[bn + n0 + j];
        }
    }
}

/* ------------------------------------------------------------------ */
/* Attention over the B axis per (t, h).  Block = 128 query rows.     */
/* No max-subtraction needed: |score| <= ~2.5 (bounded inputs).       */
/* ------------------------------------------------------------------ */
__global__ __launch_bounds__(128) void attn_kernel(
    const float* __restrict__ qkv, float* __restrict__ ctx)
{
    __shared__ float sm[128 * 65];        /* K/V tiles, reused as out stage */
    float* Ks = sm;                       /* [64][64] */
    float* Vs = sm + 4096;                /* [64][64] */

    const int tid = threadIdx.x;
    const int qt  = blockIdx.x;           /* 0..3  */
    const int h   = blockIdx.y;           /* 0..11 */
    const int t   = blockIdx.z;           /* 0..63 */

    const int q_row = qt * 128 + tid;
    const float* base = qkv + (size_t)t * B_DIM * QKV_N;

    float q[64];
    {
        const float* qp = base + (size_t)q_row * QKV_N + h * HD_DIM;
#pragma unroll
        for (int i = 0; i < 16; i++) {
            float4 v = *(const float4*)(qp + 4 * i);
            q[4*i] = v.x; q[4*i+1] = v.y; q[4*i+2] = v.z; q[4*i+3] = v.w;
        }
    }

    float acc[64] = {};
    float l = 0.f;
    const float scale = 0.125f;           /* 1/sqrt(64) */

    for (int kt = 0; kt < B_DIM; kt += 64) {
        __syncthreads();
        /* cooperatively load K,V tile: 64 keys x 64 dims each */
#pragma unroll
        for (int it = 0; it < 8; it++) {
            int f  = it * 128 + tid;
            int j  = f >> 4;
            int d4 = (f & 15) << 2;
            const float* kp = base + (size_t)(kt + j) * QKV_N + D_DIM     + h * HD_DIM + d4;
            const float* vp = base + (size_t)(kt + j) * QKV_N + 2 * D_DIM + h * HD_DIM + d4;
            *(float4*)&Ks[j * 64 + d4] = *(const float4*)kp;
            *(float4*)&Vs[j * 64 + d4] = *(const float4*)vp;
        }
        __syncthreads();

        for (int j = 0; j < 64; j++) {
            float s = 0.f;
#pragma unroll
            for (int i = 0; i < 16; i++) {
                float4 kv = *(const float4*)&Ks[j * 64 + 4 * i];
                s += q[4*i]   * kv.x + q[4*i+1] * kv.y
                   + q[4*i+2] * kv.z + q[4*i+3] * kv.w;
            }
            float p = __expf(s * scale);
            l += p;
#pragma unroll
            for (int i = 0; i < 16; i++) {
                float4 vv = *(const float4*)&Vs[j * 64 + 4 * i];
                acc[4*i]   += p * vv.x; acc[4*i+1] += p * vv.y;
                acc[4*i+2] += p * vv.z; acc[4*i+3] += p * vv.w;
            }
        }
    }

    const float inv = 1.f / l;
    __syncthreads();
#pragma unroll
    for (int d = 0; d < 64; d++) sm[tid * 65 + d] = acc[d] * inv;
    __syncthreads();

    /* coalesced writeback via smem stage */
    float* cbase = ctx + ((size_t)t * B_DIM + qt * 128) * D_DIM + h * HD_DIM;
#pragma unroll 4
    for (int it = 0; it < 64; it++) {
        int f = it * 128 + tid;
        int r = f >> 6, d = f & 63;
        cbase[(size_t)r * D_DIM + d] = sm[r * 65 + d];
    }
}

/* ------------------------------------------------------------------ */
/* adj[t,j] = (mean_i xn[t,i]) . xn[t,j], xn = out / max(||out||,eps) */
/* One block per t.                                                   */
/* ------------------------------------------------------------------ */
__global__ __launch_bounds__(256) void adj_kernel(
    const float* __restrict__ outm, float* __restrict__ adj)
{
    __shared__ float invn[B_DIM];
    __shared__ float mvec[D_DIM];

    const int t    = blockIdx.x;
    const int tid  = threadIdx.x;
    const int lane = tid & 31;
    const int warp = tid >> 5;            /* 8 warps */
    const float* O = outm + (size_t)t * B_DIM * D_DIM;

    /* phase 1: inverse norms, one warp per row */
    for (int b = warp; b < B_DIM; b += 8) {
        const float* row = O + (size_t)b * D_DIM;
        float ss = 0.f;
#pragma unroll
        for (int i = 0; i < 6; i++) {
            float4 v = *(const float4*)(row + lane * 4 + i * 128);
            ss += v.x * v.x + v.y * v.y + v.z * v.z + v.w * v.w;
        }
#pragma unroll
        for (int off = 16; off; off >>= 1)
            ss += __shfl_xor_sync(0xffffffffu, ss, off);
        if (lane == 0) invn[b] = 1.f / fmaxf(sqrtf(ss), 1e-8f);
    }
    __syncthreads();

    /* phase 2: mean normalized vector over B */
    for (int d = tid; d < D_DIM; d += 256) {
        float s = 0.f;
        for (int b = 0; b < B_DIM; b += 4) {
            s += O[(size_t)(b + 0) * D_DIM + d] * invn[b + 0]
               + O[(size_t)(b + 1) * D_DIM + d] * invn[b + 1]
               + O[(size_t)(b + 2) * D_DIM + d] * invn[b + 2]
               + O[(size_t)(b + 3) * D_DIM + d] * invn[b + 3];
        }
        mvec[d] = s * (1.f / (float)B_DIM);
    }
    __syncthreads();

    /* phase 3: adj[t,b] = (mvec . row_b) * invn[b] */
    for (int b = warp; b < B_DIM; b += 8) {
        const float* row = O + (size_t)b * D_DIM;
        float s = 0.f;
#pragma unroll
        for (int i = 0; i < 6; i++) {
            int d = lane * 4 + i * 128;
            float4 v = *(const float4*)(row + d);
            s += v.x * mvec[d] + v.y * mvec[d + 1]
               + v.z * mvec[d + 2] + v.w * mvec[d + 3];
        }
#pragma unroll
        for (int off = 16; off; off >>= 1)
            s += __shfl_xor_sync(0xffffffffu, s, off);
        if (lane == 0) adj[t * B_DIM + b] = s * invn[b];
    }
}

/* ------------------------------------------------------------------ */
extern "C" void kernel_launch(void* const* d_in, const int* in_sizes, int n_in,
                              void* d_out, int out_size)
{
    const float* node = (const float*)d_in[0];
    const float* wi   = (const float*)d_in[1];
    const float* bi   = (const float*)d_in[2];
    const float* wo   = (const float*)d_in[3];
    const float* bo   = (const float*)d_in[4];

    float *qkv, *ctx, *outm;
    cudaGetSymbolAddress((void**)&qkv,  g_qkv);
    cudaGetSymbolAddress((void**)&ctx,  g_ctx);
    cudaGetSymbolAddress((void**)&outm, g_out);

    /* 1) QKV projection: 32768 x 2304 x 768 */
    gemm_bias_kernel<<<dim3(QKV_N / TILE, M_ROWS / TILE), 256>>>(
        node, wi, bi, qkv, M_ROWS, QKV_N, D_DIM);

    /* 2) attention across B per (t,h) */
    attn_kernel<<<dim3(4, H_DIM, T_DIM), 128>>>(qkv, ctx);

    /* 3) output projection: 32768 x 768 x 768 */
    gemm_bias_kernel<<<dim3(D_DIM / TILE, M_ROWS / TILE), 256>>>(
        ctx, wo, bo, outm, M_ROWS, D_DIM, D_DIM);

    /* 4) cosine-sim mean reduction */
    adj_kernel<<<T_DIM, 256>>>(outm, (float*)d_out);
}

// round 3
// speedup vs baseline: 1.9913x; 1.9913x over previous
#include <cuda_runtime.h>
#include <math.h>
#include <stdint.h>

#define T_DIM   64
#define B_DIM   512
#define D_DIM   768
#define H_DIM   12
#define HD_DIM  64
#define M_ROWS  (T_DIM * B_DIM)    /* 32768 */
#define QKV_N   (3 * D_DIM)        /* 2304  */

/* Scratch (device globals; no allocation allowed in kernel_launch) */
__device__ float g_qkv[M_ROWS * QKV_N];   /* ~302 MB */
__device__ float g_ctx[M_ROWS * D_DIM];   /* ~100 MB */
__device__ float g_out[M_ROWS * D_DIM];   /* ~100 MB */

/* ------------------------------------------------------------------ */
/* tf32 helpers                                                        */
/* ------------------------------------------------------------------ */
__device__ __forceinline__ float tf32r(float x) {
    uint32_t u;
    asm("cvt.rna.tf32.f32 %0, %1;" : "=r"(u) : "f"(x));
    return __uint_as_float(u);
}

__device__ __forceinline__ void mma_tf32(float* c, const uint32_t* a,
                                         const uint32_t* b) {
    asm volatile(
        "mma.sync.aligned.m16n8k8.row.col.f32.tf32.tf32.f32 "
        "{%0,%1,%2,%3}, {%4,%5,%6,%7}, {%8,%9}, {%0,%1,%2,%3};\n"
        : "+f"(c[0]), "+f"(c[1]), "+f"(c[2]), "+f"(c[3])
        : "r"(a[0]), "r"(a[1]), "r"(a[2]), "r"(a[3]),
          "r"(b[0]), "r"(b[1]));
}

/* ------------------------------------------------------------------ */
/* tf32 tensor-core GEMM: C[M,N] = A[M,K] @ Bw[N,K]^T + bias[N]       */
/* Block 128x128xKT32, 8 warps (4m x 2n), warp tile 32x64.            */
/* ------------------------------------------------------------------ */
#define BM  128
#define BN  128
#define BK  32
#define PAD 4

__global__ __launch_bounds__(256) void gemm_tf32_kernel(
    const float* __restrict__ A, const float* __restrict__ Bw,
    const float* __restrict__ bias, float* __restrict__ C,
    int M, int N, int K)
{
    __shared__ float As[BM][BK + PAD];
    __shared__ float Bs[BN][BK + PAD];

    const int tid  = threadIdx.x;
    const int warp = tid >> 5;
    const int lane = tid & 31;
    const int g    = lane >> 2;       /* group id 0..7   */
    const int tg   = lane & 3;        /* thread-in-group */
    const int wm0  = (warp >> 1) * 32;
    const int wn0  = (warp & 1) * 64;
    const int bm   = blockIdx.y * BM;
    const int bn   = blockIdx.x * BN;

    float acc[2][8][4];
#pragma unroll
    for (int mt = 0; mt < 2; mt++)
#pragma unroll
        for (int nt = 0; nt < 8; nt++)
#pragma unroll
            for (int i = 0; i < 4; i++) acc[mt][nt][i] = 0.f;

    for (int k0 = 0; k0 < K; k0 += BK) {
        /* stage: 128 rows x 8 float4 per operand, tf32-rounded once */
#pragma unroll
        for (int i = 0; i < 4; i++) {
            int f = i * 256 + tid;
            int r = f >> 3;
            int c = (f & 7) << 2;
            float4 av = *(const float4*)(A  + (size_t)(bm + r) * K + k0 + c);
            float4 bv = *(const float4*)(Bw + (size_t)(bn + r) * K + k0 + c);
            av.x = tf32r(av.x); av.y = tf32r(av.y);
            av.z = tf32r(av.z); av.w = tf32r(av.w);
            bv.x = tf32r(bv.x); bv.y = tf32r(bv.y);
            bv.z = tf32r(bv.z); bv.w = tf32r(bv.w);
            *(float4*)&As[r][c] = av;
            *(float4*)&Bs[r][c] = bv;
        }
        __syncthreads();

#pragma unroll
        for (int kk = 0; kk < BK; kk += 8) {
            uint32_t bfr[8][2];
#pragma unroll
            for (int nt = 0; nt < 8; nt++) {
                const float* bp = &Bs[wn0 + nt * 8 + g][kk + tg];
                bfr[nt][0] = __float_as_uint(bp[0]);
                bfr[nt][1] = __float_as_uint(bp[4]);
            }
#pragma unroll
            for (int mt = 0; mt < 2; mt++) {
                uint32_t afr[4];
                const float* ap0 = &As[wm0 + mt * 16 + g][kk + tg];
                const float* ap1 = &As[wm0 + mt * 16 + g + 8][kk + tg];
                afr[0] = __float_as_uint(ap0[0]);
                afr[1] = __float_as_uint(ap1[0]);
                afr[2] = __float_as_uint(ap0[4]);
                afr[3] = __float_as_uint(ap1[4]);
#pragma unroll
                for (int nt = 0; nt < 8; nt++)
                    mma_tf32(acc[mt][nt], afr, bfr[nt]);
            }
        }
        __syncthreads();
    }

    /* epilogue: fragment layout c0:(g, tg*2) c1:(g, tg*2+1)
                                 c2:(g+8, tg*2) c3:(g+8, tg*2+1) */
#pragma unroll
    for (int mt = 0; mt < 2; mt++) {
#pragma unroll
        for (int nt = 0; nt < 8; nt++) {
            int row = bm + wm0 + mt * 16 + g;
            int col = bn + wn0 + nt * 8 + tg * 2;
            float b0 = bias[col], b1 = bias[col + 1];
            float2 v0 = make_float2(acc[mt][nt][0] + b0, acc[mt][nt][1] + b1);
            float2 v1 = make_float2(acc[mt][nt][2] + b0, acc[mt][nt][3] + b1);
            *(float2*)(C + (size_t)row * N + col)       = v0;
            *(float2*)(C + (size_t)(row + 8) * N + col) = v1;
        }
    }
}

/* ------------------------------------------------------------------ */
/* Attention over the B axis per (t, h).  Block = 128 query rows.     */
/* No max-subtraction needed: |score| <= ~2.5 (bounded inputs).       */
/* ------------------------------------------------------------------ */
__global__ __launch_bounds__(128) void attn_kernel(
    const float* __restrict__ qkv, float* __restrict__ ctx)
{
    __shared__ float sm[128 * 65];        /* K/V tiles, reused as out stage */
    float* Ks = sm;                       /* [64][64] */
    float* Vs = sm + 4096;                /* [64][64] */

    const int tid = threadIdx.x;
    const int qt  = blockIdx.x;           /* 0..3  */
    const int h   = blockIdx.y;           /* 0..11 */
    const int t   = blockIdx.z;           /* 0..63 */

    const int q_row = qt * 128 + tid;
    const float* base = qkv + (size_t)t * B_DIM * QKV_N;

    float q[64];
    {
        const float* qp = base + (size_t)q_row * QKV_N + h * HD_DIM;
#pragma unroll
        for (int i = 0; i < 16; i++) {
            float4 v = *(const float4*)(qp + 4 * i);
            q[4*i] = v.x; q[4*i+1] = v.y; q[4*i+2] = v.z; q[4*i+3] = v.w;
        }
    }

    float acc[64] = {};
    float l = 0.f;
    const float scale = 0.125f;           /* 1/sqrt(64) */

    for (int kt = 0; kt < B_DIM; kt += 64) {
        __syncthreads();
#pragma unroll
        for (int it = 0; it < 8; it++) {
            int f  = it * 128 + tid;
            int j  = f >> 4;
            int d4 = (f & 15) << 2;
            const float* kp = base + (size_t)(kt + j) * QKV_N + D_DIM     + h * HD_DIM + d4;
            const float* vp = base + (size_t)(kt + j) * QKV_N + 2 * D_DIM + h * HD_DIM + d4;
            *(float4*)&Ks[j * 64 + d4] = *(const float4*)kp;
            *(float4*)&Vs[j * 64 + d4] = *(const float4*)vp;
        }
        __syncthreads();

        for (int j = 0; j < 64; j++) {
            float s = 0.f;
#pragma unroll
            for (int i = 0; i < 16; i++) {
                float4 kv = *(const float4*)&Ks[j * 64 + 4 * i];
                s += q[4*i]   * kv.x + q[4*i+1] * kv.y
                   + q[4*i+2] * kv.z + q[4*i+3] * kv.w;
            }
            float p = __expf(s * scale);
            l += p;
#pragma unroll
            for (int i = 0; i < 16; i++) {
                float4 vv = *(const float4*)&Vs[j * 64 + 4 * i];
                acc[4*i]   += p * vv.x; acc[4*i+1] += p * vv.y;
                acc[4*i+2] += p * vv.z; acc[4*i+3] += p * vv.w;
            }
        }
    }

    const float inv = 1.f / l;
    __syncthreads();
#pragma unroll
    for (int d = 0; d < 64; d++) sm[tid * 65 + d] = acc[d] * inv;
    __syncthreads();

    float* cbase = ctx + ((size_t)t * B_DIM + qt * 128) * D_DIM + h * HD_DIM;
#pragma unroll 4
    for (int it = 0; it < 64; it++) {
        int f = it * 128 + tid;
        int r = f >> 6, d = f & 63;
        cbase[(size_t)r * D_DIM + d] = sm[r * 65 + d];
    }
}

/* ------------------------------------------------------------------ */
/* adj[t,j] = (mean_i xn[t,i]) . xn[t,j], xn = out / max(||out||,eps) */
/* ------------------------------------------------------------------ */
__global__ __launch_bounds__(256) void adj_kernel(
    const float* __restrict__ outm, float* __restrict__ adj)
{
    __shared__ float invn[B_DIM];
    __shared__ float mvec[D_DIM];

    const int t    = blockIdx.x;
    const int tid  = threadIdx.x;
    const int lane = tid & 31;
    const int warp = tid >> 5;
    const float* O = outm + (size_t)t * B_DIM * D_DIM;

    for (int b = warp; b < B_DIM; b += 8) {
        const float* row = O + (size_t)b * D_DIM;
        float ss = 0.f;
#pragma unroll
        for (int i = 0; i < 6; i++) {
            float4 v = *(const float4*)(row + lane * 4 + i * 128);
            ss += v.x * v.x + v.y * v.y + v.z * v.z + v.w * v.w;
        }
#pragma unroll
        for (int off = 16; off; off >>= 1)
            ss += __shfl_xor_sync(0xffffffffu, ss, off);
        if (lane == 0) invn[b] = 1.f / fmaxf(sqrtf(ss), 1e-8f);
    }
    __syncthreads();

    for (int d = tid; d < D_DIM; d += 256) {
        float s = 0.f;
        for (int b = 0; b < B_DIM; b += 4) {
            s += O[(size_t)(b + 0) * D_DIM + d] * invn[b + 0]
               + O[(size_t)(b + 1) * D_DIM + d] * invn[b + 1]
               + O[(size_t)(b + 2) * D_DIM + d] * invn[b + 2]
               + O[(size_t)(b + 3) * D_DIM + d] * invn[b + 3];
        }
        mvec[d] = s * (1.f / (float)B_DIM);
    }
    __syncthreads();

    for (int b = warp; b < B_DIM; b += 8) {
        const float* row = O + (size_t)b * D_DIM;
        float s = 0.f;
#pragma unroll
        for (int i = 0; i < 6; i++) {
            int d = lane * 4 + i * 128;
            float4 v = *(const float4*)(row + d);
            s += v.x * mvec[d] + v.y * mvec[d + 1]
               + v.z * mvec[d + 2] + v.w * mvec[d + 3];
        }
#pragma unroll
        for (int off = 16; off; off >>= 1)
            s += __shfl_xor_sync(0xffffffffu, s, off);
        if (lane == 0) adj[t * B_DIM + b] = s * invn[b];
    }
}

/* ------------------------------------------------------------------ */
extern "C" void kernel_launch(void* const* d_in, const int* in_sizes, int n_in,
                              void* d_out, int out_size)
{
    const float* node = (const float*)d_in[0];
    const float* wi   = (const float*)d_in[1];
    const float* bi   = (const float*)d_in[2];
    const float* wo   = (const float*)d_in[3];
    const float* bo   = (const float*)d_in[4];

    float *qkv, *ctx, *outm;
    cudaGetSymbolAddress((void**)&qkv,  g_qkv);
    cudaGetSymbolAddress((void**)&ctx,  g_ctx);
    cudaGetSymbolAddress((void**)&outm, g_out);

    /* 1) QKV projection: 32768 x 2304 x 768 (tf32 tensor cores) */
    gemm_tf32_kernel<<<dim3(QKV_N / BN, M_ROWS / BM), 256>>>(
        node, wi, bi, qkv, M_ROWS, QKV_N, D_DIM);

    /* 2) attention across B per (t,h) */
    attn_kernel<<<dim3(4, H_DIM, T_DIM), 128>>>(qkv, ctx);

    /* 3) output projection: 32768 x 768 x 768 (tf32 tensor cores) */
    gemm_tf32_kernel<<<dim3(D_DIM / BN, M_ROWS / BM), 256>>>(
        ctx, wo, bo, outm, M_ROWS, D_DIM, D_DIM);

    /* 4) cosine-sim mean reduction */
    adj_kernel<<<T_DIM, 256>>>(outm, (float*)d_out);
}

// round 5
// speedup vs baseline: 3.3320x; 1.6733x over previous
#include <cuda_runtime.h>
#include <math.h>
#include <stdint.h>

#define T_DIM   64
#define B_DIM   512
#define D_DIM   768
#define H_DIM   12
#define HD_DIM  64
#define M_ROWS  (T_DIM * B_DIM)    /* 32768 */
#define QKV_N   (3 * D_DIM)        /* 2304  */

/* Scratch (device globals; no allocation allowed in kernel_launch) */
__device__ float g_qkv[M_ROWS * QKV_N];
__device__ float g_ctx[M_ROWS * D_DIM];
__device__ float g_out[M_ROWS * D_DIM];

/* ------------------------------------------------------------------ */
__device__ __forceinline__ float tf32r(float x) {
    uint32_t u;
    asm("cvt.rna.tf32.f32 %0, %1;" : "=r"(u) : "f"(x));
    return __uint_as_float(u);
}

__device__ __forceinline__ void mma_tf32(float* c, const uint32_t* a,
                                         const uint32_t* b) {
    asm volatile(
        "mma.sync.aligned.m16n8k8.row.col.f32.tf32.tf32.f32 "
        "{%0,%1,%2,%3}, {%4,%5,%6,%7}, {%8,%9}, {%0,%1,%2,%3};\n"
        : "+f"(c[0]), "+f"(c[1]), "+f"(c[2]), "+f"(c[3])
        : "r"(a[0]), "r"(a[1]), "r"(a[2]), "r"(a[3]),
          "r"(b[0]), "r"(b[1]));
}

/* ------------------------------------------------------------------ */
/* tf32 tensor-core GEMM: C[M,N] = A[M,K] @ Bw[N,K]^T + bias[N]       */
/* ------------------------------------------------------------------ */
#define BM  128
#define BN  128
#define BK  32
#define PAD 4

__global__ __launch_bounds__(256) void gemm_tf32_kernel(
    const float* __restrict__ A, const float* __restrict__ Bw,
    const float* __restrict__ bias, float* __restrict__ C,
    int M, int N, int K)
{
    __shared__ float As[BM][BK + PAD];
    __shared__ float Bs[BN][BK + PAD];

    const int tid  = threadIdx.x;
    const int warp = tid >> 5;
    const int lane = tid & 31;
    const int g    = lane >> 2;
    const int tg   = lane & 3;
    const int wm0  = (warp >> 1) * 32;
    const int wn0  = (warp & 1) * 64;
    const int bm   = blockIdx.y * BM;
    const int bn   = blockIdx.x * BN;

    float acc[2][8][4];
#pragma unroll
    for (int mt = 0; mt < 2; mt++)
#pragma unroll
        for (int nt = 0; nt < 8; nt++)
#pragma unroll
            for (int i = 0; i < 4; i++) acc[mt][nt][i] = 0.f;

    for (int k0 = 0; k0 < K; k0 += BK) {
#pragma unroll
        for (int i = 0; i < 4; i++) {
            int f = i * 256 + tid;
            int r = f >> 3;
            int c = (f & 7) << 2;
            float4 av = *(const float4*)(A  + (size_t)(bm + r) * K + k0 + c);
            float4 bv = *(const float4*)(Bw + (size_t)(bn + r) * K + k0 + c);
            av.x = tf32r(av.x); av.y = tf32r(av.y);
            av.z = tf32r(av.z); av.w = tf32r(av.w);
            bv.x = tf32r(bv.x); bv.y = tf32r(bv.y);
            bv.z = tf32r(bv.z); bv.w = tf32r(bv.w);
            *(float4*)&As[r][c] = av;
            *(float4*)&Bs[r][c] = bv;
        }
        __syncthreads();

#pragma unroll
        for (int kk = 0; kk < BK; kk += 8) {
            uint32_t bfr[8][2];
#pragma unroll
            for (int nt = 0; nt < 8; nt++) {
                const float* bp = &Bs[wn0 + nt * 8 + g][kk + tg];
                bfr[nt][0] = __float_as_uint(bp[0]);
                bfr[nt][1] = __float_as_uint(bp[4]);
            }
#pragma unroll
            for (int mt = 0; mt < 2; mt++) {
                uint32_t afr[4];
                const float* ap0 = &As[wm0 + mt * 16 + g][kk + tg];
                const float* ap1 = &As[wm0 + mt * 16 + g + 8][kk + tg];
                afr[0] = __float_as_uint(ap0[0]);
                afr[1] = __float_as_uint(ap1[0]);
                afr[2] = __float_as_uint(ap0[4]);
                afr[3] = __float_as_uint(ap1[4]);
#pragma unroll
                for (int nt = 0; nt < 8; nt++)
                    mma_tf32(acc[mt][nt], afr, bfr[nt]);
            }
        }
        __syncthreads();
    }

#pragma unroll
    for (int mt = 0; mt < 2; mt++) {
#pragma unroll
        for (int nt = 0; nt < 8; nt++) {
            int row = bm + wm0 + mt * 16 + g;
            int col = bn + wn0 + nt * 8 + tg * 2;
            float b0 = bias[col], b1 = bias[col + 1];
            float2 v0 = make_float2(acc[mt][nt][0] + b0, acc[mt][nt][1] + b1);
            float2 v1 = make_float2(acc[mt][nt][2] + b0, acc[mt][nt][3] + b1);
            *(float2*)(C + (size_t)row * N + col)       = v0;
            *(float2*)(C + (size_t)(row + 8) * N + col) = v1;
        }
    }
}

/* ------------------------------------------------------------------ */
/* MMA attention over B per (t,h). Block = 128 q-rows, 8 warps x 16.  */
/* S = (Q*0.125) K^T on tensor pipe, exp, P@V on tensor pipe.         */
/* ------------------------------------------------------------------ */
#define QLD 68   /* Qs/Ps row stride: g*4+tg distinct banks */
#define KLD 68
#define VLD 72   /* transposed V read: tg*8+g distinct banks */
#define ATTN_SMEM ((128*QLD + 64*KLD + 64*VLD + 128*QLD) * 4)

__global__ __launch_bounds__(256) void attn_mma_kernel(
    const float* __restrict__ qkv, float* __restrict__ ctx)
{
    extern __shared__ float sm[];
    float* Qs = sm;                          /* [128][QLD] */
    float* Ks = Qs + 128 * QLD;              /* [64][KLD]  */
    float* Vs = Ks + 64 * KLD;               /* [64][VLD]  */
    float* Ps = Vs + 64 * VLD;               /* [128][QLD] */

    const int tid  = threadIdx.x;
    const int warp = tid >> 5;
    const int lane = tid & 31;
    const int g    = lane >> 2;
    const int tg   = lane & 3;
    const int qt   = blockIdx.x;             /* 0..3  */
    const int h    = blockIdx.y;             /* 0..11 */
    const int t    = blockIdx.z;             /* 0..63 */

    const float* base = qkv + (size_t)t * B_DIM * QKV_N;
    const int qrow0 = qt * 128;
    const int qr    = warp * 16;             /* warp's row base in tile */

    /* stage Q, scaled by 1/8 (exact) and tf32-rounded */
#pragma unroll
    for (int i = 0; i < 8; i++) {
        int f  = i * 256 + tid;
        int r  = f >> 4;
        int c4 = (f & 15) << 2;
        float4 v = *(const float4*)(base + (size_t)(qrow0 + r) * QKV_N
                                    + h * HD_DIM + c4);
        v.x = tf32r(v.x * 0.125f); v.y = tf32r(v.y * 0.125f);
        v.z = tf32r(v.z * 0.125f); v.w = tf32r(v.w * 0.125f);
        *(float4*)&Qs[r * QLD + c4] = v;
    }
    __syncthreads();

    /* Q fragments in registers: 8 k-steps x 4 regs */
    uint32_t qf[8][4];
#pragma unroll
    for (int ks = 0; ks < 8; ks++) {
        qf[ks][0] = __float_as_uint(Qs[(qr + g)     * QLD + ks * 8 + tg]);
        qf[ks][1] = __float_as_uint(Qs[(qr + g + 8) * QLD + ks * 8 + tg]);
        qf[ks][2] = __float_as_uint(Qs[(qr + g)     * QLD + ks * 8 + tg + 4]);
        qf[ks][3] = __float_as_uint(Qs[(qr + g + 8) * QLD + ks * 8 + tg + 4]);
    }

    float cacc[8][4];
#pragma unroll
    for (int nt = 0; nt < 8; nt++)
#pragma unroll
        for (int i = 0; i < 4; i++) cacc[nt][i] = 0.f;
    float l0 = 0.f, l1 = 0.f;

    for (int kt0 = 0; kt0 < B_DIM; kt0 += 64) {
        __syncthreads();   /* previous tile's Vs reads done */
#pragma unroll
        for (int i = 0; i < 4; i++) {
            int f  = i * 256 + tid;
            int r  = f >> 4;
            int c4 = (f & 15) << 2;
            const float* kp = base + (size_t)(kt0 + r) * QKV_N + D_DIM
                              + h * HD_DIM + c4;
            const float* vp = base + (size_t)(kt0 + r) * QKV_N + 2 * D_DIM
                              + h * HD_DIM + c4;
            float4 kv = *(const float4*)kp;
            float4 vv = *(const float4*)vp;
            kv.x = tf32r(kv.x); kv.y = tf32r(kv.y);
            kv.z = tf32r(kv.z); kv.w = tf32r(kv.w);
            vv.x = tf32r(vv.x); vv.y = tf32r(vv.y);
            vv.z = tf32r(vv.z); vv.w = tf32r(vv.w);
            *(float4*)&Ks[r * KLD + c4] = kv;
            *(float4*)&Vs[r * VLD + c4] = vv;
        }
        __syncthreads();

        /* S = Qs @ Ks^T : warp computes 16 x 64 */
        float sacc[8][4];
#pragma unroll
        for (int nt = 0; nt < 8; nt++)
#pragma unroll
            for (int i = 0; i < 4; i++) sacc[nt][i] = 0.f;

#pragma unroll
        for (int ks = 0; ks < 8; ks++) {
            uint32_t bf[8][2];
#pragma unroll
            for (int nt = 0; nt < 8; nt++) {
                bf[nt][0] = __float_as_uint(Ks[(nt * 8 + g) * KLD + ks * 8 + tg]);
                bf[nt][1] = __float_as_uint(Ks[(nt * 8 + g) * KLD + ks * 8 + tg + 4]);
            }
#pragma unroll
            for (int nt = 0; nt < 8; nt++)
                mma_tf32(sacc[nt], qf[ks], bf[nt]);
        }

        /* exp + row-sum + stage P (tf32) */
#pragma unroll
        for (int nt = 0; nt < 8; nt++) {
            float p0 = __expf(sacc[nt][0]);
            float p1 = __expf(sacc[nt][1]);
            float p2 = __expf(sacc[nt][2]);
            float p3 = __expf(sacc[nt][3]);
            l0 += p0 + p1;
            l1 += p2 + p3;
            int c = nt * 8 + 2 * tg;
            Ps[(qr + g)     * QLD + c]     = tf32r(p0);
            Ps[(qr + g)     * QLD + c + 1] = tf32r(p1);
            Ps[(qr + g + 8) * QLD + c]     = tf32r(p2);
            Ps[(qr + g + 8) * QLD + c + 1] = tf32r(p3);
        }
        __syncwarp();   /* warp reads only its own 16 P rows */

        /* ctx += P @ V : A = Ps rows, B = Vs transposed */
#pragma unroll
        for (int ks = 0; ks < 8; ks++) {
            uint32_t pa[4];
            pa[0] = __float_as_uint(Ps[(qr + g)     * QLD + ks * 8 + tg]);
            pa[1] = __float_as_uint(Ps[(qr + g + 8) * QLD + ks * 8 + tg]);
            pa[2] = __float_as_uint(Ps[(qr + g)     * QLD + ks * 8 + tg + 4]);
            pa[3] = __float_as_uint(Ps[(qr + g + 8) * QLD + ks * 8 + tg + 4]);
#pragma unroll
            for (int nt = 0; nt < 8; nt++) {
                uint32_t bf[2];
                bf[0] = __float_as_uint(Vs[(ks * 8 + tg)     * VLD + nt * 8 + g]);
                bf[1] = __float_as_uint(Vs[(ks * 8 + tg + 4) * VLD + nt * 8 + g]);
                mma_tf32(cacc[nt], pa, bf);
            }
        }
    }

    /* finish row sums across the 4 tg lanes of each row group */
    l0 += __shfl_xor_sync(0xffffffffu, l0, 1);
    l0 += __shfl_xor_sync(0xffffffffu, l0, 2);
    l1 += __shfl_xor_sync(0xffffffffu, l1, 1);
    l1 += __shfl_xor_sync(0xffffffffu, l1, 2);
    const float inv0 = 1.f / l0;
    const float inv1 = 1.f / l1;

    /* write ctx */
    const int row0 = t * B_DIM + qrow0 + qr + g;
#pragma unroll
    for (int nt = 0; nt < 8; nt++) {
        int col = h * HD_DIM + nt * 8 + 2 * tg;
        *(float2*)(ctx + (size_t)row0 * D_DIM + col) =
            make_float2(cacc[nt][0] * inv0, cacc[nt][1] * inv0);
        *(float2*)(ctx + (size_t)(row0 + 8) * D_DIM + col) =
            make_float2(cacc[nt][2] * inv1, cacc[nt][3] * inv1);
    }
}

/* ------------------------------------------------------------------ */
/* adj[t,j] = (mean_i xn[t,i]) . xn[t,j], xn = out / max(||out||,eps) */
/* ------------------------------------------------------------------ */
__global__ __launch_bounds__(256) void adj_kernel(
    const float* __restrict__ outm, float* __restrict__ adj)
{
    __shared__ float invn[B_DIM];
    __shared__ float mvec[D_DIM];

    const int t    = blockIdx.x;
    const int tid  = threadIdx.x;
    const int lane = tid & 31;
    const int warp = tid >> 5;
    const float* O = outm + (size_t)t * B_DIM * D_DIM;

    for (int b = warp; b < B_DIM; b += 8) {
        const float* row = O + (size_t)b * D_DIM;
        float ss = 0.f;
#pragma unroll
        for (int i = 0; i < 6; i++) {
            float4 v = *(const float4*)(row + lane * 4 + i * 128);
            ss += v.x * v.x + v.y * v.y + v.z * v.z + v.w * v.w;
        }
#pragma unroll
        for (int off = 16; off; off >>= 1)
            ss += __shfl_xor_sync(0xffffffffu, ss, off);
        if (lane == 0) invn[b] = 1.f / fmaxf(sqrtf(ss), 1e-8f);
    }
    __syncthreads();

    for (int d = tid; d < D_DIM; d += 256) {
        float s = 0.f;
        for (int b = 0; b < B_DIM; b += 4) {
            s += O[(size_t)(b + 0) * D_DIM + d] * invn[b + 0]
               + O[(size_t)(b + 1) * D_DIM + d] * invn[b + 1]
               + O[(size_t)(b + 2) * D_DIM + d] * invn[b + 2]
               + O[(size_t)(b + 3) * D_DIM + d] * invn[b + 3];
        }
        mvec[d] = s * (1.f / (float)B_DIM);
    }
    __syncthreads();

    for (int b = warp; b < B_DIM; b += 8) {
        const float* row = O + (size_t)b * D_DIM;
        float s = 0.f;
#pragma unroll
        for (int i = 0; i < 6; i++) {
            int d = lane * 4 + i * 128;
            float4 v = *(const float4*)(row + d);
            s += v.x * mvec[d] + v.y * mvec[d + 1]
               + v.z * mvec[d + 2] + v.w * mvec[d + 3];
        }
#pragma unroll
        for (int off = 16; off; off >>= 1)
            s += __shfl_xor_sync(0xffffffffu, s, off);
        if (lane == 0) adj[t * B_DIM + b] = s * invn[b];
    }
}

/* ------------------------------------------------------------------ */
extern "C" void kernel_launch(void* const* d_in, const int* in_sizes, int n_in,
                              void* d_out, int out_size)
{
    const float* node = (const float*)d_in[0];
    const float* wi   = (const float*)d_in[1];
    const float* bi   = (const float*)d_in[2];
    const float* wo   = (const float*)d_in[3];
    const float* bo   = (const float*)d_in[4];

    float *qkv, *ctx, *outm;
    cudaGetSymbolAddress((void**)&qkv,  g_qkv);
    cudaGetSymbolAddress((void**)&ctx,  g_ctx);
    cudaGetSymbolAddress((void**)&outm, g_out);

    cudaFuncSetAttribute(attn_mma_kernel,
                         cudaFuncAttributeMaxDynamicSharedMemorySize,
                         ATTN_SMEM);

    /* 1) QKV projection (tf32 tensor cores) */
    gemm_tf32_kernel<<<dim3(QKV_N / BN, M_ROWS / BM), 256>>>(
        node, wi, bi, qkv, M_ROWS, QKV_N, D_DIM);

    /* 2) attention across B per (t,h), tensor-core path */
    attn_mma_kernel<<<dim3(4, H_DIM, T_DIM), 256, ATTN_SMEM>>>(qkv, ctx);

    /* 3) output projection (tf32 tensor cores) */
    gemm_tf32_kernel<<<dim3(D_DIM / BN, M_ROWS / BM), 256>>>(
        ctx, wo, bo, outm, M_ROWS, D_DIM, D_DIM);

    /* 4) cosine-sim mean reduction */
    adj_kernel<<<T_DIM, 256>>>(outm, (float*)d_out);
}